// round 1
// baseline (speedup 1.0000x reference)
#include <cuda_runtime.h>
#include <math.h>

// Shapes (fixed for this problem)
#define D_HID 1024
#define SEQ   2048
#define BATCH 2
#define HEADS 16
#define HD    64
#define MROWS (BATCH*SEQ)          // 4096
#define OUT_MAIN (MROWS*D_HID)     // 4194304
#define ATTN_ELEMS (MROWS*HEADS*HEADS) // 1048576

// Scratch (device globals; no allocation allowed)
__device__ float g_q [MROWS*D_HID];
__device__ float g_k [MROWS*D_HID];
__device__ float g_v [MROWS*D_HID];
__device__ float g_xs[MROWS*D_HID];           // scrambled ctx (input to final GEMM)
__device__ float g_cos[SEQ*(D_HID/2)];
__device__ float g_sin[SEQ*(D_HID/2)];

// ---------------------------------------------------------------------------
// RoPE tables: inv_freq[j] = 10000^(-j/512), arg = s * inv_freq[j]
// emb = concat(freqs,freqs) so we only store the 512-wide half.
// ---------------------------------------------------------------------------
__global__ void rope_tables_kernel() {
    int idx = blockIdx.x * blockDim.x + threadIdx.x;   // over SEQ*512
    int s = idx >> 9;
    int j = idx & 511;
    // ln(10000) = 9.210340371976184
    float inv = expf(-(float)j * (9.210340371976184f / 512.0f));
    float arg = (float)s * inv;
    float sv, cv;
    sincosf(arg, &sv, &cv);
    g_cos[idx] = cv;
    g_sin[idx] = sv;
}

// ---------------------------------------------------------------------------
// Apply RoPE in place to q and k over the full hidden dim:
//   out[j]     = x[j]*cos - x[j+512]*sin
//   out[j+512] = x[j+512]*cos + x[j]*sin     (tables duplicated across halves)
// ---------------------------------------------------------------------------
__global__ void rope_apply_kernel() {
    int idx = blockIdx.x * blockDim.x + threadIdx.x;   // over MROWS*512
    int row = idx >> 9;
    int j   = idx & 511;
    int s   = row & (SEQ - 1);
    float c  = g_cos[(s << 9) | j];
    float sn = g_sin[(s << 9) | j];

    float* qp = g_q + (size_t)row * D_HID;
    float q1 = qp[j], q2 = qp[j + 512];
    qp[j]       = q1 * c - q2 * sn;
    qp[j + 512] = q2 * c + q1 * sn;

    float* kp = g_k + (size_t)row * D_HID;
    float k1 = kp[j], k2 = kp[j + 512];
    kp[j]       = k1 * c - k2 * sn;
    kp[j + 512] = k2 * c + k1 * sn;
}

// ---------------------------------------------------------------------------
// Classic smem-tiled SGEMM: C[M,N] = A[M,K] @ W[K,N] + bias
// BM=BN=128, BK=16, 256 threads, 8x8 microtile. M=4096, N=K=1024 (all divisible).
// ---------------------------------------------------------------------------
__global__ __launch_bounds__(256) void sgemm_bias(
    const float* __restrict__ A, const float* __restrict__ W,
    const float* __restrict__ bias, float* __restrict__ C)
{
    const int K = 1024, N = 1024;
    __shared__ float As[16][132];   // transposed A tile, padded vs bank conflicts
    __shared__ float Bs[16][128];

    int tid = threadIdx.x;
    int tx = tid & 15;              // 0..15 -> N microtiles
    int ty = tid >> 4;              // 0..15 -> M microtiles

    const float* Ab = A + (size_t)blockIdx.y * 128 * K;
    const float* Wb = W + blockIdx.x * 128;

    float acc[8][8];
    #pragma unroll
    for (int i = 0; i < 8; i++)
        #pragma unroll
        for (int j = 0; j < 8; j++) acc[i][j] = 0.0f;

    int arow = tid >> 2;            // 0..63 (rows arow, arow+64)
    int ac   = (tid & 3) << 2;      // float4 column within 16
    int brow = tid >> 5;            // 0..7 (rows brow, brow+8)
    int bc   = (tid & 31) << 2;     // float4 column within 128

    for (int k0 = 0; k0 < K; k0 += 16) {
        #pragma unroll
        for (int r = 0; r < 2; r++) {
            int row = arow + r * 64;
            float4 va = *(const float4*)(Ab + (size_t)row * K + k0 + ac);
            As[ac + 0][row] = va.x;
            As[ac + 1][row] = va.y;
            As[ac + 2][row] = va.z;
            As[ac + 3][row] = va.w;
        }
        #pragma unroll
        for (int r = 0; r < 2; r++) {
            int row = brow + r * 8;
            *(float4*)&Bs[row][bc] = *(const float4*)(Wb + (size_t)(k0 + row) * N + bc);
        }
        __syncthreads();

        #pragma unroll
        for (int kk = 0; kk < 16; kk++) {
            float a[8], b[8];
            #pragma unroll
            for (int i = 0; i < 8; i++) a[i] = As[kk][ty * 8 + i];
            #pragma unroll
            for (int j = 0; j < 8; j++) b[j] = Bs[kk][tx * 8 + j];
            #pragma unroll
            for (int i = 0; i < 8; i++)
                #pragma unroll
                for (int j = 0; j < 8; j++)
                    acc[i][j] = fmaf(a[i], b[j], acc[i][j]);
        }
        __syncthreads();
    }

    #pragma unroll
    for (int i = 0; i < 8; i++) {
        size_t row = (size_t)blockIdx.y * 128 + ty * 8 + i;
        int col0 = blockIdx.x * 128 + tx * 8;
        float* crow = C + row * N + col0;
        #pragma unroll
        for (int j = 0; j < 8; j++)
            crow[j] = acc[i][j] + bias[col0 + j];
    }
}

// ---------------------------------------------------------------------------
// Per-token attention across HEADS (16x16), plus scrambled ctx write:
//   ctx.transpose(0,2,1,3).reshape(B,S,D):
//     xs[b, h*128 + s/16, (s%16)*64 + d] = ctx[b, s, h, d]
// One block of 256 threads per token.
// ---------------------------------------------------------------------------
__global__ __launch_bounds__(256) void attn_kernel(float* __restrict__ attn_out,
                                                   int write_attn)
{
    __shared__ float sq[16][65];
    __shared__ float sk[16][65];
    __shared__ float sv[16][65];
    __shared__ float sc[16][17];

    int token = blockIdx.x;           // b*SEQ + s
    int tid   = threadIdx.x;

    const float* qrow = g_q + (size_t)token * D_HID;
    const float* krow = g_k + (size_t)token * D_HID;
    const float* vrow = g_v + (size_t)token * D_HID;

    for (int i = tid; i < D_HID; i += 256) {
        sq[i >> 6][i & 63] = qrow[i];
        sk[i >> 6][i & 63] = krow[i];
        sv[i >> 6][i & 63] = vrow[i];
    }
    __syncthreads();

    // scores[h][t] = (q_h . k_t) / 8
    {
        int h = tid >> 4, t = tid & 15;
        float acc = 0.0f;
        #pragma unroll
        for (int d = 0; d < HD; d++)
            acc = fmaf(sq[h][d], sk[t][d], acc);
        sc[h][t] = acc * 0.125f;
    }
    __syncthreads();

    // softmax over t (row-wise, 16 threads)
    if (tid < 16) {
        float m = -1e30f;
        #pragma unroll
        for (int t = 0; t < 16; t++) m = fmaxf(m, sc[tid][t]);
        float sum = 0.0f;
        #pragma unroll
        for (int t = 0; t < 16; t++) {
            float e = expf(sc[tid][t] - m);
            sc[tid][t] = e;
            sum += e;
        }
        float r = 1.0f / sum;
        #pragma unroll
        for (int t = 0; t < 16; t++) sc[tid][t] *= r;
    }
    __syncthreads();

    if (write_attn)
        attn_out[(size_t)token * 256 + tid] = sc[tid >> 4][tid & 15];

    // ctx[h][d] = sum_t attn[h][t] * v[t][d]; write scrambled
    int o0 = tid * 4;
    int h  = o0 >> 6;
    int d0 = o0 & 63;
    int b  = token >> 11;         // /SEQ
    int s  = token & (SEQ - 1);
    float* xrow = g_xs + ((size_t)b * SEQ + (h * 128 + (s >> 4))) * D_HID
                       + ((s & 15) << 6);
    #pragma unroll
    for (int jj = 0; jj < 4; jj++) {
        int d = d0 + jj;
        float acc = 0.0f;
        #pragma unroll
        for (int t = 0; t < 16; t++)
            acc = fmaf(sc[h][t], sv[t][d], acc);
        xrow[d] = acc;
    }
}

// ---------------------------------------------------------------------------
extern "C" void kernel_launch(void* const* d_in, const int* in_sizes, int n_in,
                              void* d_out, int out_size)
{
    const float* inputs  = (const float*)d_in[0];
    const float* context = (const float*)d_in[1];
    const float* Wq = (const float*)d_in[2];
    const float* bq = (const float*)d_in[3];
    const float* Wk = (const float*)d_in[4];
    const float* bk = (const float*)d_in[5];
    const float* Wv = (const float*)d_in[6];
    const float* bv = (const float*)d_in[7];
    const float* Wo = (const float*)d_in[8];
    const float* bo = (const float*)d_in[9];
    float* out = (float*)d_out;

    float *q, *k, *v, *xs;
    cudaGetSymbolAddress((void**)&q,  g_q);
    cudaGetSymbolAddress((void**)&k,  g_k);
    cudaGetSymbolAddress((void**)&v,  g_v);
    cudaGetSymbolAddress((void**)&xs, g_xs);

    // 1) RoPE tables
    rope_tables_kernel<<<(SEQ * 512) / 256, 256>>>();

    // 2) q, k, v projections
    dim3 gemm_grid(D_HID / 128, MROWS / 128);   // (8, 32)
    sgemm_bias<<<gemm_grid, 256>>>(inputs,  Wq, bq, q);
    sgemm_bias<<<gemm_grid, 256>>>(context, Wk, bk, k);
    sgemm_bias<<<gemm_grid, 256>>>(context, Wv, bv, v);

    // 3) RoPE on q and k (in place)
    rope_apply_kernel<<<(MROWS * 512) / 256, 256>>>();

    // 4) per-token head-attention; write attn to d_out tail; write scrambled ctx
    int write_attn = (out_size >= OUT_MAIN + ATTN_ELEMS) ? 1 : 0;
    attn_kernel<<<MROWS, 256>>>(out + OUT_MAIN, write_attn);

    // 5) final projection on scrambled ctx
    sgemm_bias<<<gemm_grid, 256>>>(xs, Wo, bo, out);
}

// round 3
// speedup vs baseline: 2.0923x; 2.0923x over previous
#include <cuda_runtime.h>
#include <cuda_bf16.h>
#include <math.h>
#include <stdint.h>

// Shapes (fixed)
#define D_HID 1024
#define SEQ   2048
#define BATCH 2
#define HEADS 16
#define HD    64
#define MROWS (BATCH*SEQ)                 // 4096
#define OUT_MAIN (MROWS*D_HID)            // 4194304
#define ATTN_ELEMS (MROWS*HEADS*HEADS)    // 1048576

// fp32 scratch
__device__ float g_q [MROWS*D_HID];
__device__ float g_k [MROWS*D_HID];
__device__ float g_v [MROWS*D_HID];
__device__ float g_xs[MROWS*D_HID];
__device__ float g_cos[SEQ*(D_HID/2)];
__device__ float g_sin[SEQ*(D_HID/2)];

// bf16 split planes
__device__ __nv_bfloat16 g_in_h[MROWS*D_HID];
__device__ __nv_bfloat16 g_in_l[MROWS*D_HID];
__device__ __nv_bfloat16 g_cx_h[MROWS*D_HID];
__device__ __nv_bfloat16 g_cx_l[MROWS*D_HID];
__device__ __nv_bfloat16 g_xs_h[MROWS*D_HID];
__device__ __nv_bfloat16 g_xs_l[MROWS*D_HID];
__device__ __nv_bfloat16 g_wt_h[D_HID*D_HID];   // W^T hi  [N][K]
__device__ __nv_bfloat16 g_wt_l[D_HID*D_HID];   // W^T lo

__device__ __forceinline__ uint32_t smem_u32(const void* p) {
    uint32_t a;
    asm("{ .reg .u64 t; cvta.to.shared.u64 t, %1; cvt.u32.u64 %0, t; }"
        : "=r"(a) : "l"(p));
    return a;
}

// ---------------------------------------------------------------------------
// RoPE tables
// ---------------------------------------------------------------------------
__global__ void rope_tables_kernel() {
    int idx = blockIdx.x * blockDim.x + threadIdx.x;   // SEQ*512
    int s = idx >> 9;
    int j = idx & 511;
    float inv = expf(-(float)j * (9.210340371976184f / 512.0f));
    float arg = (float)s * inv;
    float sv, cv;
    sincosf(arg, &sv, &cv);
    g_cos[idx] = cv;
    g_sin[idx] = sv;
}

// ---------------------------------------------------------------------------
// RoPE in place on q,k over full hidden dim
// ---------------------------------------------------------------------------
__global__ void rope_apply_kernel() {
    int idx = blockIdx.x * blockDim.x + threadIdx.x;   // MROWS*512
    int row = idx >> 9;
    int j   = idx & 511;
    int s   = row & (SEQ - 1);
    float c  = g_cos[(s << 9) | j];
    float sn = g_sin[(s << 9) | j];

    float* qp = g_q + (size_t)row * D_HID;
    float q1 = qp[j], q2 = qp[j + 512];
    qp[j]       = q1 * c - q2 * sn;
    qp[j + 512] = q2 * c + q1 * sn;

    float* kp = g_k + (size_t)row * D_HID;
    float k1 = kp[j], k2 = kp[j + 512];
    kp[j]       = k1 * c - k2 * sn;
    kp[j + 512] = k2 * c + k1 * sn;
}

// ---------------------------------------------------------------------------
// fp32 -> (bf16 hi, bf16 lo) split, elementwise (vectorized x4)
// ---------------------------------------------------------------------------
__global__ void conv_split(const float4* __restrict__ src,
                           uint2* __restrict__ h, uint2* __restrict__ l, int n4)
{
    int idx = blockIdx.x * blockDim.x + threadIdx.x;
    if (idx >= n4) return;
    float4 v = src[idx];
    __nv_bfloat16 hx = __float2bfloat16_rn(v.x);
    __nv_bfloat16 hy = __float2bfloat16_rn(v.y);
    __nv_bfloat16 hz = __float2bfloat16_rn(v.z);
    __nv_bfloat16 hw = __float2bfloat16_rn(v.w);
    __nv_bfloat16 lx = __float2bfloat16_rn(v.x - __bfloat162float(hx));
    __nv_bfloat16 ly = __float2bfloat16_rn(v.y - __bfloat162float(hy));
    __nv_bfloat16 lz = __float2bfloat16_rn(v.z - __bfloat162float(hz));
    __nv_bfloat16 lw = __float2bfloat16_rn(v.w - __bfloat162float(hw));
    __nv_bfloat162 h01; h01.x = hx; h01.y = hy;
    __nv_bfloat162 h23; h23.x = hz; h23.y = hw;
    __nv_bfloat162 l01; l01.x = lx; l01.y = ly;
    __nv_bfloat162 l23; l23.x = lz; l23.y = lw;
    uint2 uh, ul;
    uh.x = *(uint32_t*)&h01; uh.y = *(uint32_t*)&h23;
    ul.x = *(uint32_t*)&l01; ul.y = *(uint32_t*)&l23;
    h[idx] = uh;
    l[idx] = ul;
}

// ---------------------------------------------------------------------------
// Weight transpose + split: wt_h/l[n][k] = split(W[k][n])
// ---------------------------------------------------------------------------
__global__ __launch_bounds__(256) void conv_wt(const float* __restrict__ W,
                                               __nv_bfloat16* __restrict__ h,
                                               __nv_bfloat16* __restrict__ l)
{
    __shared__ float t[32][33];
    int x0 = blockIdx.x * 32;
    int y0 = blockIdx.y * 32;
    int tx = threadIdx.x, ty = threadIdx.y;   // (32,8)
    #pragma unroll
    for (int j = 0; j < 4; j++)
        t[ty + 8 * j][tx] = W[(size_t)(y0 + ty + 8 * j) * D_HID + x0 + tx];
    __syncthreads();
    #pragma unroll
    for (int j = 0; j < 4; j++) {
        int r = ty + 8 * j;
        float v = t[tx][r];
        __nv_bfloat16 hv = __float2bfloat16_rn(v);
        __nv_bfloat16 lv = __float2bfloat16_rn(v - __bfloat162float(hv));
        size_t o = (size_t)(x0 + r) * D_HID + y0 + tx;
        h[o] = hv;
        l[o] = lv;
    }
}

// ---------------------------------------------------------------------------
// bf16 3-term split GEMM: C[M,N] = A @ W + bias, A hi/lo [M][K], Wt hi/lo [N][K]
// CTA tile 128x128, K-chunk 32, 4-stage cp.async pipeline, 8 warps (64x32 each)
// mma.sync.m16n8k16 row.col bf16 -> fp32
// ---------------------------------------------------------------------------
#define KC 32
#define NSTAGE 4
#define PLANE 8192                  // 128 rows * 32 bf16 * 2B
#define STAGE_BYTES (4*PLANE)       // Ah, Al, Bh, Bl
#define GEMM_SMEM (NSTAGE*STAGE_BYTES)   // 131072
#define NCHUNK (D_HID/KC)           // 32

#define LDSM4(r0,r1,r2,r3,addr) \
    asm volatile("ldmatrix.sync.aligned.m8n8.x4.shared.b16 {%0,%1,%2,%3}, [%4];" \
        : "=r"(r0), "=r"(r1), "=r"(r2), "=r"(r3) : "r"(addr))

#define MMA_BF16(d, a, b0v, b1v) \
    asm volatile("mma.sync.aligned.m16n8k16.row.col.f32.bf16.bf16.f32 " \
        "{%0,%1,%2,%3}, {%4,%5,%6,%7}, {%8,%9}, {%0,%1,%2,%3};" \
        : "+f"((d)[0]), "+f"((d)[1]), "+f"((d)[2]), "+f"((d)[3]) \
        : "r"((a)[0]), "r"((a)[1]), "r"((a)[2]), "r"((a)[3]), "r"(b0v), "r"(b1v))

__global__ __launch_bounds__(256, 1)
void gemm_bf16_split(const __nv_bfloat16* __restrict__ Ah,
                     const __nv_bfloat16* __restrict__ Al,
                     const __nv_bfloat16* __restrict__ Bh,
                     const __nv_bfloat16* __restrict__ Bl,
                     const float* __restrict__ bias, float* __restrict__ C)
{
    extern __shared__ char smem[];
    uint32_t sb = smem_u32(smem);
    int tid = threadIdx.x, lane = tid & 31, wid = tid >> 5;
    int wm = (wid >> 2) * 64;       // warp M offset within CTA tile
    int wn = (wid & 3) * 32;        // warp N offset

    const __nv_bfloat16* gp[4] = {Ah, Al, Bh, Bl};
    int rbase[4] = {(int)blockIdx.y * 128, (int)blockIdx.y * 128,
                    (int)blockIdx.x * 128, (int)blockIdx.x * 128};

    // loader lane mapping: each thread copies 2 x 16B per plane per chunk
    int lrow = tid >> 1;            // 0..127
    int lb0  = (tid & 1) * 2;       // block pair {0,1} or {2,3}
    int lsw  = (lrow >> 1) & 3;

    // ldmatrix lane address precompute: A (per m-tile)
    uint32_t aOff[4]; int aSw[4];
    #pragma unroll
    for (int mt = 0; mt < 4; mt++) {
        int r = wm + mt * 16 + (lane & 7) + ((lane >> 3) & 1) * 8;
        aOff[mt] = r * 64;
        aSw[mt] = (r >> 1) & 3;
    }
    // B (per pack of two 8-wide n-tiles)
    int g = lane >> 3;
    uint32_t bOff[2]; int bSw[2];
    #pragma unroll
    for (int pk = 0; pk < 2; pk++) {
        int r = wn + pk * 16 + ((g >> 1) << 3) + (lane & 7);
        bOff[pk] = r * 64;
        bSw[pk] = (r >> 1) & 3;
    }
    int aKb = lane >> 4;            // 0/1 -> k-block within k16 step
    int bKb = g & 1;

    float acc[4][4][4];
    #pragma unroll
    for (int i = 0; i < 4; i++)
        #pragma unroll
        for (int j = 0; j < 4; j++)
            #pragma unroll
            for (int c = 0; c < 4; c++) acc[i][j][c] = 0.0f;

    // ---- pipelined main loop ----
    #define LOAD_CHUNK(chunk, stage) do {                                        \
        uint32_t dbase = sb + (stage) * STAGE_BYTES + lrow * 64;                 \
        _Pragma("unroll")                                                        \
        for (int p = 0; p < 4; p++) {                                            \
            const __nv_bfloat16* srcp = gp[p]                                    \
                + (size_t)(rbase[p] + lrow) * D_HID + (chunk) * KC;              \
            uint32_t dpl = dbase + p * PLANE;                                    \
            _Pragma("unroll")                                                    \
            for (int j = 0; j < 2; j++) {                                        \
                int blk = lb0 + j;                                               \
                uint32_t dst = dpl + ((blk ^ lsw) << 4);                         \
                asm volatile("cp.async.cg.shared.global [%0], [%1], 16;"         \
                             :: "r"(dst), "l"(srcp + blk * 8));                  \
            }                                                                    \
        }                                                                        \
    } while (0)

    #pragma unroll
    for (int s = 0; s < NSTAGE - 1; s++) {
        LOAD_CHUNK(s, s);
        asm volatile("cp.async.commit_group;");
    }

    for (int i = 0; i < NCHUNK; i++) {
        asm volatile("cp.async.wait_group %0;" :: "n"(NSTAGE - 2));
        __syncthreads();

        if (i + NSTAGE - 1 < NCHUNK)
            LOAD_CHUNK(i + NSTAGE - 1, (i + NSTAGE - 1) & (NSTAGE - 1));
        asm volatile("cp.async.commit_group;");

        uint32_t st = sb + (i & (NSTAGE - 1)) * STAGE_BYTES;
        #pragma unroll
        for (int s = 0; s < 2; s++) {
            uint32_t bh[8], bl[8];
            #pragma unroll
            for (int pk = 0; pk < 2; pk++) {
                uint32_t ad = st + 2 * PLANE + bOff[pk]
                            + (((2 * s + bKb) ^ bSw[pk]) << 4);
                LDSM4(bh[pk*4+0], bh[pk*4+1], bh[pk*4+2], bh[pk*4+3], ad);
                LDSM4(bl[pk*4+0], bl[pk*4+1], bl[pk*4+2], bl[pk*4+3], ad + PLANE);
            }
            uint32_t ah[4][4], al[4][4];
            #pragma unroll
            for (int mt = 0; mt < 4; mt++) {
                uint32_t ad = st + aOff[mt] + (((2 * s + aKb) ^ aSw[mt]) << 4);
                LDSM4(ah[mt][0], ah[mt][1], ah[mt][2], ah[mt][3], ad);
                LDSM4(al[mt][0], al[mt][1], al[mt][2], al[mt][3], ad + PLANE);
            }
            #pragma unroll
            for (int mt = 0; mt < 4; mt++) {
                #pragma unroll
                for (int nt = 0; nt < 4; nt++) {
                    MMA_BF16(acc[mt][nt], ah[mt], bh[nt*2], bh[nt*2+1]);
                    MMA_BF16(acc[mt][nt], ah[mt], bl[nt*2], bl[nt*2+1]);
                    MMA_BF16(acc[mt][nt], al[mt], bh[nt*2], bh[nt*2+1]);
                }
            }
        }
    }

    // ---- epilogue ----
    #pragma unroll
    for (int mt = 0; mt < 4; mt++) {
        int row0 = blockIdx.y * 128 + wm + mt * 16 + (lane >> 2);
        #pragma unroll
        for (int nt = 0; nt < 4; nt++) {
            int col = blockIdx.x * 128 + wn + nt * 8 + (lane & 3) * 2;
            float b0 = bias[col], b1 = bias[col + 1];
            float2 v0, v1;
            v0.x = acc[mt][nt][0] + b0; v0.y = acc[mt][nt][1] + b1;
            v1.x = acc[mt][nt][2] + b0; v1.y = acc[mt][nt][3] + b1;
            *(float2*)(C + (size_t)row0 * D_HID + col) = v0;
            *(float2*)(C + (size_t)(row0 + 8) * D_HID + col) = v1;
        }
    }
}

// ---------------------------------------------------------------------------
// Per-token attention over heads (16x16) + scrambled ctx write
//   xs[b, h*128 + s/16, (s%16)*64 + d] = ctx[b, s, h, d]
// ---------------------------------------------------------------------------
__global__ __launch_bounds__(256) void attn_kernel(float* __restrict__ attn_out,
                                                   int write_attn)
{
    __shared__ float sq[16][65];
    __shared__ float sk[16][65];
    __shared__ float sv[16][65];
    __shared__ float sc[16][17];

    int token = blockIdx.x;
    int tid   = threadIdx.x;

    const float* qrow = g_q + (size_t)token * D_HID;
    const float* krow = g_k + (size_t)token * D_HID;
    const float* vrow = g_v + (size_t)token * D_HID;

    for (int i = tid; i < D_HID; i += 256) {
        sq[i >> 6][i & 63] = qrow[i];
        sk[i >> 6][i & 63] = krow[i];
        sv[i >> 6][i & 63] = vrow[i];
    }
    __syncthreads();

    {
        int h = tid >> 4, t = tid & 15;
        float acc = 0.0f;
        #pragma unroll
        for (int d = 0; d < HD; d++)
            acc = fmaf(sq[h][d], sk[t][d], acc);
        sc[h][t] = acc * 0.125f;
    }
    __syncthreads();

    if (tid < 16) {
        float m = -1e30f;
        #pragma unroll
        for (int t = 0; t < 16; t++) m = fmaxf(m, sc[tid][t]);
        float sum = 0.0f;
        #pragma unroll
        for (int t = 0; t < 16; t++) {
            float e = expf(sc[tid][t] - m);
            sc[tid][t] = e;
            sum += e;
        }
        float r = 1.0f / sum;
        #pragma unroll
        for (int t = 0; t < 16; t++) sc[tid][t] *= r;
    }
    __syncthreads();

    if (write_attn)
        attn_out[(size_t)token * 256 + tid] = sc[tid >> 4][tid & 15];

    int o0 = tid * 4;
    int h  = o0 >> 6;
    int d0 = o0 & 63;
    int b  = token >> 11;
    int s  = token & (SEQ - 1);
    float* xrow = g_xs + ((size_t)b * SEQ + (h * 128 + (s >> 4))) * D_HID
                       + ((s & 15) << 6);
    #pragma unroll
    for (int jj = 0; jj < 4; jj++) {
        int d = d0 + jj;
        float acc = 0.0f;
        #pragma unroll
        for (int t = 0; t < 16; t++)
            acc = fmaf(sc[h][t], sv[t][d], acc);
        xrow[d] = acc;
    }
}

// ---------------------------------------------------------------------------
extern "C" void kernel_launch(void* const* d_in, const int* in_sizes, int n_in,
                              void* d_out, int out_size)
{
    const float* inputs  = (const float*)d_in[0];
    const float* context = (const float*)d_in[1];
    const float* Wq = (const float*)d_in[2];
    const float* bq = (const float*)d_in[3];
    const float* Wk = (const float*)d_in[4];
    const float* bk = (const float*)d_in[5];
    const float* Wv = (const float*)d_in[6];
    const float* bv = (const float*)d_in[7];
    const float* Wo = (const float*)d_in[8];
    const float* bo = (const float*)d_in[9];
    float* out = (float*)d_out;

    float *q, *k, *v, *xs;
    __nv_bfloat16 *inh, *inl, *cxh, *cxl, *xsh, *xsl, *wth, *wtl;
    cudaGetSymbolAddress((void**)&q,   g_q);
    cudaGetSymbolAddress((void**)&k,   g_k);
    cudaGetSymbolAddress((void**)&v,   g_v);
    cudaGetSymbolAddress((void**)&xs,  g_xs);
    cudaGetSymbolAddress((void**)&inh, g_in_h);
    cudaGetSymbolAddress((void**)&inl, g_in_l);
    cudaGetSymbolAddress((void**)&cxh, g_cx_h);
    cudaGetSymbolAddress((void**)&cxl, g_cx_l);
    cudaGetSymbolAddress((void**)&xsh, g_xs_h);
    cudaGetSymbolAddress((void**)&xsl, g_xs_l);
    cudaGetSymbolAddress((void**)&wth, g_wt_h);
    cudaGetSymbolAddress((void**)&wtl, g_wt_l);

    cudaFuncSetAttribute(gemm_bf16_split,
                         cudaFuncAttributeMaxDynamicSharedMemorySize, GEMM_SMEM);

    dim3 tgrid(32, 32), tblk(32, 8);
    dim3 ggrid(D_HID / 128, MROWS / 128);   // (8, 32)
    int n4 = MROWS * D_HID / 4;

    // 1) tables + operand conversions
    rope_tables_kernel<<<(SEQ * 512) / 256, 256>>>();
    conv_split<<<(n4 + 255) / 256, 256>>>((const float4*)inputs,  (uint2*)inh, (uint2*)inl, n4);
    conv_split<<<(n4 + 255) / 256, 256>>>((const float4*)context, (uint2*)cxh, (uint2*)cxl, n4);

    // 2) q, k, v projections (tensor-core bf16-split GEMM)
    conv_wt<<<tgrid, tblk>>>(Wq, wth, wtl);
    gemm_bf16_split<<<ggrid, 256, GEMM_SMEM>>>(inh, inl, wth, wtl, bq, q);
    conv_wt<<<tgrid, tblk>>>(Wk, wth, wtl);
    gemm_bf16_split<<<ggrid, 256, GEMM_SMEM>>>(cxh, cxl, wth, wtl, bk, k);
    conv_wt<<<tgrid, tblk>>>(Wv, wth, wtl);
    gemm_bf16_split<<<ggrid, 256, GEMM_SMEM>>>(cxh, cxl, wth, wtl, bv, v);

    // 3) RoPE
    rope_apply_kernel<<<(MROWS * 512) / 256, 256>>>();

    // 4) head-attention + scrambled ctx
    int write_attn = (out_size >= OUT_MAIN + ATTN_ELEMS) ? 1 : 0;
    attn_kernel<<<MROWS, 256>>>(out + OUT_MAIN, write_attn);

    // 5) final projection
    conv_split<<<(n4 + 255) / 256, 256>>>((const float4*)xs, (uint2*)xsh, (uint2*)xsl, n4);
    conv_wt<<<tgrid, tblk>>>(Wo, wth, wtl);
    gemm_bf16_split<<<ggrid, 256, GEMM_SMEM>>>(xsh, xsl, wth, wtl, bo, out);
}

// round 4
// speedup vs baseline: 2.3173x; 1.1075x over previous
#include <cuda_runtime.h>
#include <cuda_bf16.h>
#include <math.h>
#include <stdint.h>

// Shapes (fixed)
#define D_HID 1024
#define SEQ   2048
#define BATCH 2
#define HEADS 16
#define HD    64
#define MROWS (BATCH*SEQ)                 // 4096
#define OUT_MAIN (MROWS*D_HID)            // 4194304
#define ATTN_ELEMS (MROWS*HEADS*HEADS)    // 1048576

// fp32 scratch
__device__ float g_q [MROWS*D_HID];
__device__ float g_k [MROWS*D_HID];
__device__ float g_v [MROWS*D_HID];
__device__ float g_cos[SEQ*(D_HID/2)];
__device__ float g_sin[SEQ*(D_HID/2)];

// bf16 split planes
__device__ __nv_bfloat16 g_in_h[MROWS*D_HID];
__device__ __nv_bfloat16 g_in_l[MROWS*D_HID];
__device__ __nv_bfloat16 g_cx_h[MROWS*D_HID];
__device__ __nv_bfloat16 g_cx_l[MROWS*D_HID];
__device__ __nv_bfloat16 g_xs_h[MROWS*D_HID];
__device__ __nv_bfloat16 g_xs_l[MROWS*D_HID];
__device__ __nv_bfloat16 g_wt_h[4*D_HID*D_HID];   // W^T hi, 4 weights
__device__ __nv_bfloat16 g_wt_l[4*D_HID*D_HID];   // W^T lo

__device__ __forceinline__ uint32_t smem_u32(const void* p) {
    uint32_t a;
    asm("{ .reg .u64 t; cvta.to.shared.u64 t, %1; cvt.u32.u64 %0, t; }"
        : "=r"(a) : "l"(p));
    return a;
}

// ---------------------------------------------------------------------------
// RoPE tables
// ---------------------------------------------------------------------------
__global__ void rope_tables_kernel() {
    int idx = blockIdx.x * blockDim.x + threadIdx.x;   // SEQ*512
    int s = idx >> 9;
    int j = idx & 511;
    float inv = expf(-(float)j * (9.210340371976184f / 512.0f));
    float arg = (float)s * inv;
    float sv, cv;
    sincosf(arg, &sv, &cv);
    g_cos[idx] = cv;
    g_sin[idx] = sv;
}

// ---------------------------------------------------------------------------
// fp32 -> bf16 hi/lo split for inputs (z=0) and context (z=1), vectorized
// ---------------------------------------------------------------------------
__global__ void conv_split2(const float4* __restrict__ s0,
                            const float4* __restrict__ s1, int n4)
{
    int idx = blockIdx.x * blockDim.x + threadIdx.x;
    if (idx >= n4) return;
    const float4* src = blockIdx.y ? s1 : s0;
    uint2* h = (uint2*)(blockIdx.y ? g_cx_h : g_in_h);
    uint2* l = (uint2*)(blockIdx.y ? g_cx_l : g_in_l);
    float4 v = src[idx];
    __nv_bfloat16 hx = __float2bfloat16_rn(v.x);
    __nv_bfloat16 hy = __float2bfloat16_rn(v.y);
    __nv_bfloat16 hz = __float2bfloat16_rn(v.z);
    __nv_bfloat16 hw = __float2bfloat16_rn(v.w);
    __nv_bfloat16 lx = __float2bfloat16_rn(v.x - __bfloat162float(hx));
    __nv_bfloat16 ly = __float2bfloat16_rn(v.y - __bfloat162float(hy));
    __nv_bfloat16 lz = __float2bfloat16_rn(v.z - __bfloat162float(hz));
    __nv_bfloat16 lw = __float2bfloat16_rn(v.w - __bfloat162float(hw));
    __nv_bfloat162 h01; h01.x = hx; h01.y = hy;
    __nv_bfloat162 h23; h23.x = hz; h23.y = hw;
    __nv_bfloat162 l01; l01.x = lx; l01.y = ly;
    __nv_bfloat162 l23; l23.x = lz; l23.y = lw;
    uint2 uh, ul;
    uh.x = *(uint32_t*)&h01; uh.y = *(uint32_t*)&h23;
    ul.x = *(uint32_t*)&l01; ul.y = *(uint32_t*)&l23;
    h[idx] = uh;
    l[idx] = ul;
}

// ---------------------------------------------------------------------------
// Weight transpose + split for all 4 weights (z selects), out at z*D*D
// ---------------------------------------------------------------------------
__global__ __launch_bounds__(256) void conv_wt4(const float* __restrict__ W0,
                                                const float* __restrict__ W1,
                                                const float* __restrict__ W2,
                                                const float* __restrict__ W3)
{
    __shared__ float t[32][33];
    int z = blockIdx.z;
    const float* W = (z == 0) ? W0 : (z == 1) ? W1 : (z == 2) ? W2 : W3;
    __nv_bfloat16* h = g_wt_h + (size_t)z * D_HID * D_HID;
    __nv_bfloat16* l = g_wt_l + (size_t)z * D_HID * D_HID;
    int x0 = blockIdx.x * 32;
    int y0 = blockIdx.y * 32;
    int tx = threadIdx.x, ty = threadIdx.y;   // (32,8)
    #pragma unroll
    for (int j = 0; j < 4; j++)
        t[ty + 8 * j][tx] = W[(size_t)(y0 + ty + 8 * j) * D_HID + x0 + tx];
    __syncthreads();
    #pragma unroll
    for (int j = 0; j < 4; j++) {
        int r = ty + 8 * j;
        float v = t[tx][r];
        __nv_bfloat16 hv = __float2bfloat16_rn(v);
        __nv_bfloat16 lv = __float2bfloat16_rn(v - __bfloat162float(hv));
        size_t o = (size_t)(x0 + r) * D_HID + y0 + tx;
        h[o] = hv;
        l[o] = lv;
    }
}

// ---------------------------------------------------------------------------
// bf16 3-term split GEMM: C[M,N] = A @ W + bias
//   CTA tile 256x128, 8 warps of 64x64, K-chunk 32, 4-stage cp.async.
//   A hi/lo [M][K] bf16, Wt hi/lo [N][K] bf16, fp32 accum.
// ---------------------------------------------------------------------------
#define KC 32
#define NSTAGE 4
#define PLANE_A 16384                    // 256 rows * 64B
#define PLANE_B 8192                     // 128 rows * 64B
#define STAGE_BYTES (2*PLANE_A + 2*PLANE_B)  // 49152
#define GEMM_SMEM (NSTAGE*STAGE_BYTES)       // 196608
#define NCHUNK (D_HID/KC)                // 32

#define LDSM4(r0,r1,r2,r3,addr) \
    asm volatile("ldmatrix.sync.aligned.m8n8.x4.shared.b16 {%0,%1,%2,%3}, [%4];" \
        : "=r"(r0), "=r"(r1), "=r"(r2), "=r"(r3) : "r"(addr))

#define MMA_BF16(d, a, b0v, b1v) \
    asm volatile("mma.sync.aligned.m16n8k16.row.col.f32.bf16.bf16.f32 " \
        "{%0,%1,%2,%3}, {%4,%5,%6,%7}, {%8,%9}, {%0,%1,%2,%3};" \
        : "+f"((d)[0]), "+f"((d)[1]), "+f"((d)[2]), "+f"((d)[3]) \
        : "r"((a)[0]), "r"((a)[1]), "r"((a)[2]), "r"((a)[3]), "r"(b0v), "r"(b1v))

__global__ __launch_bounds__(256, 1)
void gemm_bf16_split(const __nv_bfloat16* __restrict__ Ah,
                     const __nv_bfloat16* __restrict__ Al,
                     const __nv_bfloat16* __restrict__ Bh,
                     const __nv_bfloat16* __restrict__ Bl,
                     const float* __restrict__ bias, float* __restrict__ C)
{
    extern __shared__ char smem[];
    uint32_t sb = smem_u32(smem);
    int tid = threadIdx.x, lane = tid & 31, wid = tid >> 5;
    int wm = (wid & 3) * 64;        // warp M offset (4 warps over 256)
    int wn = (wid >> 2) * 64;       // warp N offset (2 warps over 128)

    int mbaseA = blockIdx.y * 256;
    int nbaseB = blockIdx.x * 128;

    // loader mapping
    int lrow = tid >> 1;            // 0..127
    int lb0  = (tid & 1) * 2;       // 16B block pair

    // ldmatrix lane address precompute
    uint32_t aOff[4]; int aSw[4];
    #pragma unroll
    for (int mt = 0; mt < 4; mt++) {
        int r = wm + mt * 16 + (lane & 7) + ((lane >> 3) & 1) * 8;
        aOff[mt] = r * 64;
        aSw[mt] = (r >> 1) & 3;
    }
    int g = lane >> 3;
    uint32_t bOff[4]; int bSw[4];
    #pragma unroll
    for (int pk = 0; pk < 4; pk++) {
        int r = wn + pk * 16 + ((g >> 1) << 3) + (lane & 7);
        bOff[pk] = r * 64;
        bSw[pk] = (r >> 1) & 3;
    }
    int aKb = lane >> 4;
    int bKb = g & 1;

    float acc[4][8][4];
    #pragma unroll
    for (int i = 0; i < 4; i++)
        #pragma unroll
        for (int j = 0; j < 8; j++)
            #pragma unroll
            for (int c = 0; c < 4; c++) acc[i][j][c] = 0.0f;

    #define LOAD_CHUNK(chunk, stage) do {                                        \
        uint32_t st0 = sb + (stage) * STAGE_BYTES;                               \
        int kk = (chunk) * KC;                                                   \
        _Pragma("unroll")                                                        \
        for (int rr = 0; rr < 2; rr++) {                                         \
            int r = lrow + rr * 128;                                             \
            int sw = (r >> 1) & 3;                                               \
            const __nv_bfloat16* sh = Ah + (size_t)(mbaseA + r) * D_HID + kk;    \
            const __nv_bfloat16* sl = Al + (size_t)(mbaseA + r) * D_HID + kk;    \
            _Pragma("unroll")                                                    \
            for (int j = 0; j < 2; j++) {                                        \
                int blk = lb0 + j;                                               \
                uint32_t d = st0 + r * 64 + ((blk ^ sw) << 4);                   \
                asm volatile("cp.async.cg.shared.global [%0], [%1], 16;"         \
                             :: "r"(d), "l"(sh + blk * 8));                      \
                asm volatile("cp.async.cg.shared.global [%0], [%1], 16;"         \
                             :: "r"(d + PLANE_A), "l"(sl + blk * 8));            \
            }                                                                    \
        }                                                                        \
        {                                                                        \
            int r = lrow;                                                        \
            int sw = (r >> 1) & 3;                                               \
            const __nv_bfloat16* sh = Bh + (size_t)(nbaseB + r) * D_HID + kk;    \
            const __nv_bfloat16* sl = Bl + (size_t)(nbaseB + r) * D_HID + kk;    \
            _Pragma("unroll")                                                    \
            for (int j = 0; j < 2; j++) {                                        \
                int blk = lb0 + j;                                               \
                uint32_t d = st0 + 2 * PLANE_A + r * 64 + ((blk ^ sw) << 4);     \
                asm volatile("cp.async.cg.shared.global [%0], [%1], 16;"         \
                             :: "r"(d), "l"(sh + blk * 8));                      \
                asm volatile("cp.async.cg.shared.global [%0], [%1], 16;"         \
                             :: "r"(d + PLANE_B), "l"(sl + blk * 8));            \
            }                                                                    \
        }                                                                        \
    } while (0)

    #pragma unroll
    for (int s = 0; s < NSTAGE - 1; s++) {
        LOAD_CHUNK(s, s);
        asm volatile("cp.async.commit_group;");
    }

    for (int i = 0; i < NCHUNK; i++) {
        asm volatile("cp.async.wait_group %0;" :: "n"(NSTAGE - 2));
        __syncthreads();

        if (i + NSTAGE - 1 < NCHUNK)
            LOAD_CHUNK(i + NSTAGE - 1, (i + NSTAGE - 1) & (NSTAGE - 1));
        asm volatile("cp.async.commit_group;");

        uint32_t st = sb + (i & (NSTAGE - 1)) * STAGE_BYTES;
        #pragma unroll
        for (int s = 0; s < 2; s++) {
            uint32_t bh[16], bl[16];
            #pragma unroll
            for (int pk = 0; pk < 4; pk++) {
                uint32_t ad = st + 2 * PLANE_A + bOff[pk]
                            + (((2 * s + bKb) ^ bSw[pk]) << 4);
                LDSM4(bh[pk*4+0], bh[pk*4+1], bh[pk*4+2], bh[pk*4+3], ad);
                LDSM4(bl[pk*4+0], bl[pk*4+1], bl[pk*4+2], bl[pk*4+3], ad + PLANE_B);
            }
            uint32_t ah[4][4], al[4][4];
            #pragma unroll
            for (int mt = 0; mt < 4; mt++) {
                uint32_t ad = st + aOff[mt] + (((2 * s + aKb) ^ aSw[mt]) << 4);
                LDSM4(ah[mt][0], ah[mt][1], ah[mt][2], ah[mt][3], ad);
                LDSM4(al[mt][0], al[mt][1], al[mt][2], al[mt][3], ad + PLANE_A);
            }
            #pragma unroll
            for (int mt = 0; mt < 4; mt++) {
                #pragma unroll
                for (int nt = 0; nt < 8; nt++) {
                    MMA_BF16(acc[mt][nt], ah[mt], bh[nt*2], bh[nt*2+1]);
                    MMA_BF16(acc[mt][nt], ah[mt], bl[nt*2], bl[nt*2+1]);
                    MMA_BF16(acc[mt][nt], al[mt], bh[nt*2], bh[nt*2+1]);
                }
            }
        }
    }

    // epilogue
    #pragma unroll
    for (int mt = 0; mt < 4; mt++) {
        int row0 = blockIdx.y * 256 + wm + mt * 16 + (lane >> 2);
        #pragma unroll
        for (int nt = 0; nt < 8; nt++) {
            int col = blockIdx.x * 128 + wn + nt * 8 + (lane & 3) * 2;
            float b0 = bias[col], b1 = bias[col + 1];
            float2 v0, v1;
            v0.x = acc[mt][nt][0] + b0; v0.y = acc[mt][nt][1] + b1;
            v1.x = acc[mt][nt][2] + b0; v1.y = acc[mt][nt][3] + b1;
            *(float2*)(C + (size_t)row0 * D_HID + col) = v0;
            *(float2*)(C + (size_t)(row0 + 8) * D_HID + col) = v1;
        }
    }
}

// ---------------------------------------------------------------------------
// Fused: RoPE(q,k) + per-token head attention (16x16) + attn output +
// scrambled ctx written directly as bf16 hi/lo planes.
//   xs[b, h*128 + s/16, (s%16)*64 + d] = ctx[b, s, h, d]
// ---------------------------------------------------------------------------
__global__ __launch_bounds__(256) void attn_fused_kernel(float* __restrict__ attn_out,
                                                         int write_attn)
{
    __shared__ float sq[16][65];
    __shared__ float sk[16][65];
    __shared__ float sv[16][65];
    __shared__ float sc[16][17];

    int token = blockIdx.x;
    int tid   = threadIdx.x;
    int s     = token & (SEQ - 1);
    int b     = token >> 11;

    const float* qrow = g_q + (size_t)token * D_HID;
    const float* krow = g_k + (size_t)token * D_HID;
    const float* vrow = g_v + (size_t)token * D_HID;

    for (int i = tid; i < D_HID; i += 256) {
        int j  = i & 511;
        float c  = g_cos[(s << 9) | j];
        float sn = g_sin[(s << 9) | j];
        float qa = qrow[i], qb = qrow[i ^ 512];
        float ka = krow[i], kb = krow[i ^ 512];
        float rq, rk;
        if (i < 512) { rq = qa * c - qb * sn; rk = ka * c - kb * sn; }
        else         { rq = qa * c + qb * sn; rk = ka * c + kb * sn; }
        sq[i >> 6][i & 63] = rq;
        sk[i >> 6][i & 63] = rk;
        sv[i >> 6][i & 63] = vrow[i];
    }
    __syncthreads();

    {
        int h = tid >> 4, t = tid & 15;
        float acc = 0.0f;
        #pragma unroll
        for (int d = 0; d < HD; d++)
            acc = fmaf(sq[h][d], sk[t][d], acc);
        sc[h][t] = acc * 0.125f;
    }
    __syncthreads();

    if (tid < 16) {
        float m = -1e30f;
        #pragma unroll
        for (int t = 0; t < 16; t++) m = fmaxf(m, sc[tid][t]);
        float sum = 0.0f;
        #pragma unroll
        for (int t = 0; t < 16; t++) {
            float e = expf(sc[tid][t] - m);
            sc[tid][t] = e;
            sum += e;
        }
        float r = 1.0f / sum;
        #pragma unroll
        for (int t = 0; t < 16; t++) sc[tid][t] *= r;
    }
    __syncthreads();

    if (write_attn)
        attn_out[(size_t)token * 256 + tid] = sc[tid >> 4][tid & 15];

    // ctx + scrambled bf16 split write
    int o0 = tid * 4;
    int h  = o0 >> 6;
    int d0 = o0 & 63;
    size_t xbase = ((size_t)b * SEQ + (h * 128 + (s >> 4))) * D_HID
                 + ((s & 15) << 6);
    __nv_bfloat16* xh = g_xs_h + xbase;
    __nv_bfloat16* xl = g_xs_l + xbase;
    #pragma unroll
    for (int jj = 0; jj < 4; jj++) {
        int d = d0 + jj;
        float acc = 0.0f;
        #pragma unroll
        for (int t = 0; t < 16; t++)
            acc = fmaf(sc[h][t], sv[t][d], acc);
        __nv_bfloat16 hv = __float2bfloat16_rn(acc);
        __nv_bfloat16 lv = __float2bfloat16_rn(acc - __bfloat162float(hv));
        xh[d] = hv;
        xl[d] = lv;
    }
}

// ---------------------------------------------------------------------------
extern "C" void kernel_launch(void* const* d_in, const int* in_sizes, int n_in,
                              void* d_out, int out_size)
{
    const float* inputs  = (const float*)d_in[0];
    const float* context = (const float*)d_in[1];
    const float* Wq = (const float*)d_in[2];
    const float* bq = (const float*)d_in[3];
    const float* Wk = (const float*)d_in[4];
    const float* bk = (const float*)d_in[5];
    const float* Wv = (const float*)d_in[6];
    const float* bv = (const float*)d_in[7];
    const float* Wo = (const float*)d_in[8];
    const float* bo = (const float*)d_in[9];
    float* out = (float*)d_out;

    float *q, *k, *v;
    __nv_bfloat16 *inh, *inl, *cxh, *cxl, *xsh, *xsl, *wth, *wtl;
    cudaGetSymbolAddress((void**)&q,   g_q);
    cudaGetSymbolAddress((void**)&k,   g_k);
    cudaGetSymbolAddress((void**)&v,   g_v);
    cudaGetSymbolAddress((void**)&inh, g_in_h);
    cudaGetSymbolAddress((void**)&inl, g_in_l);
    cudaGetSymbolAddress((void**)&cxh, g_cx_h);
    cudaGetSymbolAddress((void**)&cxl, g_cx_l);
    cudaGetSymbolAddress((void**)&xsh, g_xs_h);
    cudaGetSymbolAddress((void**)&xsl, g_xs_l);
    cudaGetSymbolAddress((void**)&wth, g_wt_h);
    cudaGetSymbolAddress((void**)&wtl, g_wt_l);

    cudaFuncSetAttribute(gemm_bf16_split,
                         cudaFuncAttributeMaxDynamicSharedMemorySize, GEMM_SMEM);

    const size_t WSZ = (size_t)D_HID * D_HID;
    dim3 ggrid(D_HID / 128, MROWS / 256);   // (8, 16) = 128 CTAs
    int n4 = MROWS * D_HID / 4;

    // 1) tables + operand conversions (batched)
    rope_tables_kernel<<<(SEQ * 512) / 256, 256>>>();
    {
        dim3 cg((n4 + 255) / 256, 2);
        conv_split2<<<cg, 256>>>((const float4*)inputs, (const float4*)context, n4);
    }
    {
        dim3 wgrid(32, 32, 4), wblk(32, 8);
        conv_wt4<<<wgrid, wblk>>>(Wq, Wk, Wv, Wo);
    }

    // 2) q, k, v projections
    gemm_bf16_split<<<ggrid, 256, GEMM_SMEM>>>(inh, inl, wth + 0*WSZ, wtl + 0*WSZ, bq, q);
    gemm_bf16_split<<<ggrid, 256, GEMM_SMEM>>>(cxh, cxl, wth + 1*WSZ, wtl + 1*WSZ, bk, k);
    gemm_bf16_split<<<ggrid, 256, GEMM_SMEM>>>(cxh, cxl, wth + 2*WSZ, wtl + 2*WSZ, bv, v);

    // 3) fused RoPE + head-attention + scrambled bf16 ctx
    int write_attn = (out_size >= OUT_MAIN + ATTN_ELEMS) ? 1 : 0;
    attn_fused_kernel<<<MROWS, 256>>>(out + OUT_MAIN, write_attn);

    // 4) final projection
    gemm_bf16_split<<<ggrid, 256, GEMM_SMEM>>>(xsh, xsl, wth + 3*WSZ, wtl + 3*WSZ, bo, out);
}